// round 1
// baseline (speedup 1.0000x reference)
#include <cuda_runtime.h>
#include <math.h>

#define NA 20000
#define PE 320000
#define FD 128
#define RD 64
#define MD 32
#define DX 480
#define DH 256

// ---------------- scratch (device globals; no allocation allowed) ----------
__device__ float g_u [PE*3];
__device__ float g_X [(size_t)PE*DX];   // [rbf 0:64 | a_ui a_uj a_ij a_ii a_jj 64:224 | si 224:352 | sj 352:480]
__device__ float g_H [(size_t)PE*DH];   // [eq hidden 0:128 | inv hidden 128:256]
__device__ float g_G [(size_t)PE*64];
__device__ float g_Mi[(size_t)PE*FD];
__device__ float g_v0[NA*96];
__device__ float g_v1[NA*96];
__device__ float g_W1eff[DX*DH];
__device__ float g_b1c[DH];
__device__ float g_hbuf[NA*2*FD];
__device__ float g_tbuf[NA*FD];

__device__ __forceinline__ float silu_f(float x){ return x/(1.f+__expf(-x)); }

__device__ __forceinline__ void ffma2(float2 &d, float2 a, float2 b){
#if defined(__CUDA_ARCH__) && __CUDA_ARCH__ >= 1000
    asm("fma.rn.f32x2 %0, %1, %2, %0;"
        : "+l"(*reinterpret_cast<unsigned long long*>(&d))
        : "l"(*reinterpret_cast<unsigned long long*>(&a)),
          "l"(*reinterpret_cast<unsigned long long*>(&b)));
#else
    d.x = fmaf(a.x,b.x,d.x);
    d.y = fmaf(a.y,b.y,d.y);
#endif
}

// ---------------- small prep kernels ---------------------------------------
__global__ void prep_u_k(const float* __restrict__ vectors, const float* __restrict__ dist){
    int idx = blockIdx.x*blockDim.x + threadIdx.x;
    if(idx >= PE*3) return;
    g_u[idx] = vectors[idx] / (dist[idx/3] + 0.001f);
}

// Build W1eff (480x256) = fused [eq | inv] first-layer weights with Wrbf folded in.
// Row blocks: 0:64 rbf, 64:224 a_* , 224:352 si, 352:480 sj.
__global__ void prep_w1_k(int b, const float* __restrict__ Wrbf,
                          const float* __restrict__ eqW1, const float* __restrict__ eqb1,
                          const float* __restrict__ invW1all, const float* __restrict__ invb1all){
    int idx = blockIdx.x*blockDim.x + threadIdx.x;
    if(idx >= DX*DH) return;
    int r = idx / DH, c = idx % DH;
    bool inv = (c >= FD);
    int cc = c & (FD-1);
    const float* W1 = inv ? (invW1all + (size_t)b*448*FD) : eqW1;
    float acc = 0.f;
    if(r < 64){
        #pragma unroll 8
        for(int k=0;k<32;k++) acc += Wrbf[r*32+k]*W1[k*FD+cc];           // e-rows via Wrbf[rbf]
    } else if(r < 224){
        int ar = r-64;
        if(inv || b==1) acc = W1[(32+ar)*FD+cc];                          // a_* rows (eq0: zero)
    } else if(r < 352){
        int sr = r-224;
        int baseRow = (inv || b==1) ? (192+sr) : (32+sr);                 // si rows
        acc = W1[baseRow*FD+cc];
        #pragma unroll 8
        for(int k=0;k<32;k++) acc += Wrbf[(64+sr)*32+k]*W1[k*FD+cc];
    } else {
        int jr = r-352;
        int baseRow = (inv || b==1) ? (320+jr) : (160+jr);                // sj rows
        acc = W1[baseRow*FD+cc];
        #pragma unroll 8
        for(int k=0;k<32;k++) acc += Wrbf[(192+jr)*32+k]*W1[k*FD+cc];
    }
    g_W1eff[idx] = acc;
    if(r==0) g_b1c[c] = inv ? invb1all[b*FD+cc] : eqb1[cc];
}

// Per-edge feature row: gather si/sj, compute a_* dot products, copy rbf.
__global__ void edge_x_k(const float* __restrict__ s, const float* __restrict__ v_in,
                         const float* __restrict__ rbfs,
                         const int* __restrict__ idx_i, const int* __restrict__ idx_j){
    int p = blockIdx.x*4 + threadIdx.y;   // 4 warps/block, 1 edge/warp
    int lane = threadIdx.x;
    int i = idx_i[p], j = idx_j[p];
    float* xr = g_X + (size_t)p*DX;
    for(int t=lane;t<RD;t+=32) xr[t] = rbfs[(size_t)p*RD+t];
    float u0 = g_u[p*3+0], u1 = g_u[p*3+1], u2 = g_u[p*3+2];
    const float* vi  = v_in + (size_t)i*96;
    const float* vjp = v_in + (size_t)j*96;
    float vi0=vi[lane],  vi1=vi[32+lane],  vi2=vi[64+lane];
    float vj0=vjp[lane], vj1=vjp[32+lane], vj2=vjp[64+lane];
    xr[ 64+lane] = u0*vi0 + u1*vi1 + u2*vi2;   // a_ui
    xr[ 96+lane] = u0*vj0 + u1*vj1 + u2*vj2;   // a_uj
    xr[128+lane] = vi0*vj0 + vi1*vj1 + vi2*vj2; // a_ij
    xr[160+lane] = vi0*vi0 + vi1*vi1 + vi2*vi2; // a_ii
    xr[192+lane] = vj0*vj0 + vj1*vj1 + vj2*vj2; // a_jj
    const float* si = s + (size_t)i*FD;
    const float* sj = s + (size_t)j*FD;
    for(int t=lane;t<FD;t+=32){ xr[224+t]=si[t]; xr[352+t]=sj[t]; }
}

// ---------------- SGEMM: C = [accum +] act(A@B + bias), B row-major (K,N) --
__global__ __launch_bounds__(256) void sgemm_k(
    const float* __restrict__ A, int lda,
    const float* __restrict__ B, int ldb,
    const float* __restrict__ bias,
    float* __restrict__ C, int ldc,
    int Mr, int Nc, int K, int act, int accum)
{
    __shared__ float As[8][128];
    __shared__ float Bs[8][132];
    const int tid = threadIdx.x;
    const int bm = blockIdx.y*128, bn = blockIdx.x*128;
    const int tx = tid & 15, ty = tid >> 4;
    float2 acc[4][8];
    #pragma unroll
    for(int q=0;q<4;q++)
        #pragma unroll
        for(int j=0;j<8;j++) acc[q][j] = make_float2(0.f,0.f);

    for(int k0=0;k0<K;k0+=8){
        #pragma unroll
        for(int t=0;t<4;t++){
            int i = t*256+tid; int r = i>>3, kk = i&7;
            int gr = bm+r;
            As[kk][r] = (gr<Mr) ? A[(size_t)gr*lda + k0+kk] : 0.f;
        }
        #pragma unroll
        for(int t=0;t<4;t++){
            int i = t*256+tid; int kk = i>>7, c = i&127;
            int gc = bn+c;
            Bs[kk][c] = (gc<Nc) ? B[(size_t)(k0+kk)*ldb + gc] : 0.f;
        }
        __syncthreads();
        #pragma unroll
        for(int kk=0;kk<8;kk++){
            float4 a0 = *(const float4*)&As[kk][ty*8];
            float4 a1 = *(const float4*)&As[kk][ty*8+4];
            float4 b0 = *(const float4*)&Bs[kk][tx*8];
            float4 b1 = *(const float4*)&Bs[kk][tx*8+4];
            float2 a2[4] = {{a0.x,a0.y},{a0.z,a0.w},{a1.x,a1.y},{a1.z,a1.w}};
            float  rb[8] = {b0.x,b0.y,b0.z,b0.w,b1.x,b1.y,b1.z,b1.w};
            #pragma unroll
            for(int q=0;q<4;q++)
                #pragma unroll
                for(int j=0;j<8;j++)
                    ffma2(acc[q][j], a2[q], make_float2(rb[j],rb[j]));
        }
        __syncthreads();
    }
    #pragma unroll
    for(int q=0;q<4;q++){
        #pragma unroll
        for(int sgn=0;sgn<2;sgn++){
            int gr = bm + ty*8 + q*2 + sgn;
            if(gr >= Mr) continue;
            #pragma unroll
            for(int j=0;j<8;j++){
                int gc = bn + tx*8 + j;
                if(gc >= Nc) continue;
                float x = sgn ? acc[q][j].y : acc[q][j].x;
                if(bias)  x += bias[gc];
                if(act)   x = silu_f(x);
                if(accum) C[(size_t)gr*ldc+gc] += x;
                else      C[(size_t)gr*ldc+gc]  = x;
            }
        }
    }
}

// ---------------- segment-sum scatters (idx_i sorted) -----------------------
__global__ void m_scatter_k(float* __restrict__ s_out,
                            const int* __restrict__ idx_i,
                            const float* __restrict__ cutoffs){
    int f  = threadIdx.x;          // 128 threads = feature dim
    int p0 = blockIdx.x*128;       // 128 consecutive edges
    float acc = 0.f; int cur = idx_i[p0];
    for(int e=0;e<128;e++){
        int p = p0+e;
        int ii = idx_i[p];
        if(ii != cur){ atomicAdd(&s_out[(size_t)cur*FD+f], acc); acc = 0.f; cur = ii; }
        acc += g_Mi[(size_t)p*FD+f] * cutoffs[p];
    }
    atomicAdd(&s_out[(size_t)cur*FD+f], acc);
}

__global__ void dv_scatter_k(const float* __restrict__ v_in, float* __restrict__ v_out,
                             const int* __restrict__ idx_i, const int* __restrict__ idx_j,
                             const float* __restrict__ cutoffs){
    int t = threadIdx.x;           // 96 threads: d = t>>5, m = t&31
    int m = t & 31, d = t >> 5;
    int p0 = blockIdx.x*128;
    float acc = 0.f; int cur = idx_i[p0];
    for(int e=0;e<128;e++){
        int p = p0+e;
        int ii = idx_i[p];
        if(ii != cur){ atomicAdd(&v_out[(size_t)cur*96+t], acc); acc = 0.f; cur = ii; }
        int j = idx_j[p];
        float g0 = g_G[(size_t)p*64 + m];
        float g1 = g_G[(size_t)p*64 + 32 + m];
        float vj = v_in[(size_t)j*96 + t];
        acc += (g0*g_u[p*3+d] + g1*vj) * cutoffs[p];
    }
    atomicAdd(&v_out[(size_t)cur*96+t], acc);
}

__global__ void copy_s_to_h_k(const float* __restrict__ s){
    int idx = blockIdx.x*blockDim.x + threadIdx.x;
    if(idx >= NA*FD) return;
    g_hbuf[(idx/FD)*2*FD + (idx%FD)] = s[idx];
}

// ---------------- launch ----------------------------------------------------
extern "C" void kernel_launch(void* const* d_in, const int* in_sizes, int n_in,
                              void* d_out, int out_size)
{
    const float* features = (const float*)d_in[0];
    const float* distances= (const float*)d_in[1];
    const float* vectors  = (const float*)d_in[2];
    const float* cutoffs  = (const float*)d_in[3];
    const float* rbfs     = (const float*)d_in[4];
    const int*   idx_i    = (const int*)  d_in[5];
    const int*   idx_j    = (const int*)  d_in[6];
    const float* Wrbf     = (const float*)d_in[7];
    const float* Wemb     = (const float*)d_in[8];
    const float* eq0_W1   = (const float*)d_in[9];
    const float* eq0_b1   = (const float*)d_in[10];
    const float* eq0_W2   = (const float*)d_in[11];
    const float* eq1_W1   = (const float*)d_in[12];
    const float* eq1_b1   = (const float*)d_in[13];
    const float* eq1_W2   = (const float*)d_in[14];
    const float* inv_W1   = (const float*)d_in[15];
    const float* inv_b1   = (const float*)d_in[16];
    const float* inv_W2   = (const float*)d_in[17];
    const float* inv_b2   = (const float*)d_in[18];
    const float* upd_W1   = (const float*)d_in[19];
    const float* upd_b1   = (const float*)d_in[20];
    const float* upd_W2   = (const float*)d_in[21];
    const float* upd_b2   = (const float*)d_in[22];

    float* out_s = (float*)d_out;
    float* out_v = out_s + (size_t)NA*FD;

    float *pX,*pH,*pG,*pMi,*pv0,*pv1,*pW1,*pb1,*ph,*pt;
    cudaGetSymbolAddress((void**)&pX,  g_X);
    cudaGetSymbolAddress((void**)&pH,  g_H);
    cudaGetSymbolAddress((void**)&pG,  g_G);
    cudaGetSymbolAddress((void**)&pMi, g_Mi);
    cudaGetSymbolAddress((void**)&pv0, g_v0);
    cudaGetSymbolAddress((void**)&pv1, g_v1);
    cudaGetSymbolAddress((void**)&pW1, g_W1eff);
    cudaGetSymbolAddress((void**)&pb1, g_b1c);
    cudaGetSymbolAddress((void**)&ph,  g_hbuf);
    cudaGetSymbolAddress((void**)&pt,  g_tbuf);

    // init: s = features, v = 0
    cudaMemcpyAsync(out_s, features, (size_t)NA*FD*sizeof(float), cudaMemcpyDeviceToDevice, 0);
    cudaMemsetAsync(pv0, 0, (size_t)NA*96*sizeof(float), 0);
    prep_u_k<<<(PE*3+255)/256, 256>>>(vectors, distances);

    for(int b=0;b<2;b++){
        const float* eqW1 = b ? eq1_W1 : eq0_W1;
        const float* eqb1 = b ? eq1_b1 : eq0_b1;
        const float* eqW2 = b ? eq1_W2 : eq0_W2;
        float* v_in  = b ? pv1  : pv0;
        float* v_out = b ? out_v: pv1;

        prep_w1_k<<<(DX*DH+255)/256, 256>>>(b, Wrbf, eqW1, eqb1, inv_W1, inv_b1);
        edge_x_k<<<PE/4, dim3(32,4)>>>(out_s, v_in, rbfs, idx_i, idx_j);

        // H = silu(X @ W1eff + b1)    (P,480)@(480,256)
        { dim3 g(DH/128, PE/128);
          sgemm_k<<<g,256>>>(pX, DX, pW1, DH, pb1, pH, DH, PE, DH, DX, 1, 0); }
        // G = H_eq @ eqW2             (P,128)@(128,64)
        { dim3 g(1, PE/128);
          sgemm_k<<<g,256>>>(pH, DH, eqW2, 64, nullptr, pG, 64, PE, 64, FD, 0, 0); }
        // Mi = silu(H_inv @ invW2 + invb2)  (P,128)@(128,128)
        { dim3 g(1, PE/128);
          sgemm_k<<<g,256>>>(pH+FD, DH, inv_W2 + (size_t)b*FD*FD, FD,
                             inv_b2 + b*FD, pMi, FD, PE, FD, FD, 1, 0); }

        // v_out = v_in + segment_sum(dv)
        cudaMemcpyAsync(v_out, v_in, (size_t)NA*96*sizeof(float), cudaMemcpyDeviceToDevice, 0);
        dv_scatter_k<<<PE/128, 96>>>(v_in, v_out, idx_i, idx_j, cutoffs);
        // s += segment_sum(m)
        m_scatter_k<<<PE/128, 128>>>(out_s, idx_i, cutoffs);

        // node update: h = [s, s@Wemb]; s += silu(silu(h@U1+b1)@U2+b2)
        copy_s_to_h_k<<<(NA*FD+255)/256, 256>>>(out_s);
        { dim3 g(1, (NA+127)/128);
          sgemm_k<<<g,256>>>(out_s, FD, Wemb, FD, nullptr, ph+FD, 2*FD, NA, FD, FD, 0, 0); }
        { dim3 g(1, (NA+127)/128);
          sgemm_k<<<g,256>>>(ph, 2*FD, upd_W1 + (size_t)b*2*FD*FD, FD,
                             upd_b1 + b*FD, pt, FD, NA, FD, 2*FD, 1, 0); }
        { dim3 g(1, (NA+127)/128);
          sgemm_k<<<g,256>>>(pt, FD, upd_W2 + (size_t)b*FD*FD, FD,
                             upd_b2 + b*FD, out_s, FD, NA, FD, FD, 1, 1); }
    }
    (void)in_sizes; (void)n_in; (void)out_size;
}

// round 2
// speedup vs baseline: 1.0007x; 1.0007x over previous
#include <cuda_runtime.h>
#include <math.h>

#define NA 20000
#define PE 320000
#define FD 128
#define RD 64
#define MD 32
#define DX 480
#define DH 256

// ---------------- scratch (device globals; no allocation allowed) ----------
__device__ float g_u [PE*3];
__device__ float g_X [(size_t)PE*DX];   // [rbf 0:64 | a_ui a_uj a_ij a_ii a_jj 64:224 | si 224:352 | sj 352:480]
__device__ float g_H [(size_t)PE*DH];   // [eq hidden 0:128 | inv hidden 128:256]
__device__ float g_G [(size_t)PE*64];
__device__ float g_Mi[(size_t)PE*FD];
__device__ float g_v0[NA*96];
__device__ float g_v1[NA*96];
__device__ float g_W1eff[DX*DH];
__device__ float g_b1c[DH];
__device__ float g_hbuf[NA*2*FD];
__device__ float g_tbuf[NA*FD];

__device__ __forceinline__ float silu_f(float x){ return x/(1.f+__expf(-x)); }

__device__ __forceinline__ void ffma2(float2 &d, float2 a, float2 b){
#if defined(__CUDA_ARCH__) && __CUDA_ARCH__ >= 1000
    asm("fma.rn.f32x2 %0, %1, %2, %0;"
        : "+l"(*reinterpret_cast<unsigned long long*>(&d))
        : "l"(*reinterpret_cast<unsigned long long*>(&a)),
          "l"(*reinterpret_cast<unsigned long long*>(&b)));
#else
    d.x = fmaf(a.x,b.x,d.x);
    d.y = fmaf(a.y,b.y,d.y);
#endif
}

// ---------------- small prep kernels ---------------------------------------
__global__ void prep_u_k(const float* __restrict__ vectors, const float* __restrict__ dist){
    int idx = blockIdx.x*blockDim.x + threadIdx.x;
    if(idx >= PE*3) return;
    g_u[idx] = vectors[idx] / (dist[idx/3] + 0.001f);
}

// Build W1eff (480x256) = fused [eq | inv] first-layer weights with Wrbf folded in.
// Row blocks: 0:64 rbf, 64:224 a_* , 224:352 si, 352:480 sj.
__global__ void prep_w1_k(int b, const float* __restrict__ Wrbf,
                          const float* __restrict__ eqW1, const float* __restrict__ eqb1,
                          const float* __restrict__ invW1all, const float* __restrict__ invb1all){
    int idx = blockIdx.x*blockDim.x + threadIdx.x;
    if(idx >= DX*DH) return;
    int r = idx / DH, c = idx % DH;
    bool inv = (c >= FD);
    int cc = c & (FD-1);
    const float* W1 = inv ? (invW1all + (size_t)b*448*FD) : eqW1;
    float acc = 0.f;
    if(r < 64){
        #pragma unroll 8
        for(int k=0;k<32;k++) acc += Wrbf[r*32+k]*W1[k*FD+cc];           // e-rows via Wrbf[rbf]
    } else if(r < 224){
        int ar = r-64;
        if(inv || b==1) acc = W1[(32+ar)*FD+cc];                          // a_* rows (eq0: zero)
    } else if(r < 352){
        int sr = r-224;
        int baseRow = (inv || b==1) ? (192+sr) : (32+sr);                 // si rows
        acc = W1[baseRow*FD+cc];
        #pragma unroll 8
        for(int k=0;k<32;k++) acc += Wrbf[(64+sr)*32+k]*W1[k*FD+cc];
    } else {
        int jr = r-352;
        int baseRow = (inv || b==1) ? (320+jr) : (160+jr);                // sj rows
        acc = W1[baseRow*FD+cc];
        #pragma unroll 8
        for(int k=0;k<32;k++) acc += Wrbf[(192+jr)*32+k]*W1[k*FD+cc];
    }
    g_W1eff[idx] = acc;
    if(r==0) g_b1c[c] = inv ? invb1all[b*FD+cc] : eqb1[cc];
}

// Per-edge feature row: gather si/sj, compute a_* dot products, copy rbf.
__global__ void edge_x_k(const float* __restrict__ s, const float* __restrict__ v_in,
                         const float* __restrict__ rbfs,
                         const int* __restrict__ idx_i, const int* __restrict__ idx_j){
    int p = blockIdx.x*4 + threadIdx.y;   // 4 warps/block, 1 edge/warp
    int lane = threadIdx.x;
    int i = idx_i[p], j = idx_j[p];
    float* xr = g_X + (size_t)p*DX;
    for(int t=lane;t<RD;t+=32) xr[t] = rbfs[(size_t)p*RD+t];
    float u0 = g_u[p*3+0], u1 = g_u[p*3+1], u2 = g_u[p*3+2];
    const float* vi  = v_in + (size_t)i*96;
    const float* vjp = v_in + (size_t)j*96;
    float vi0=vi[lane],  vi1=vi[32+lane],  vi2=vi[64+lane];
    float vj0=vjp[lane], vj1=vjp[32+lane], vj2=vjp[64+lane];
    xr[ 64+lane] = u0*vi0 + u1*vi1 + u2*vi2;   // a_ui
    xr[ 96+lane] = u0*vj0 + u1*vj1 + u2*vj2;   // a_uj
    xr[128+lane] = vi0*vj0 + vi1*vj1 + vi2*vj2; // a_ij
    xr[160+lane] = vi0*vi0 + vi1*vi1 + vi2*vi2; // a_ii
    xr[192+lane] = vj0*vj0 + vj1*vj1 + vj2*vj2; // a_jj
    const float* si = s + (size_t)i*FD;
    const float* sj = s + (size_t)j*FD;
    for(int t=lane;t<FD;t+=32){ xr[224+t]=si[t]; xr[352+t]=sj[t]; }
}

// ---------------- SGEMM: C = [accum +] act(A@B + bias), B row-major (K,N) --
__global__ __launch_bounds__(256) void sgemm_k(
    const float* __restrict__ A, int lda,
    const float* __restrict__ B, int ldb,
    const float* __restrict__ bias,
    float* __restrict__ C, int ldc,
    int Mr, int Nc, int K, int act, int accum)
{
    __shared__ float As[8][128];
    __shared__ float Bs[8][132];
    const int tid = threadIdx.x;
    const int bm = blockIdx.y*128, bn = blockIdx.x*128;
    const int tx = tid & 15, ty = tid >> 4;
    float2 acc[4][8];
    #pragma unroll
    for(int q=0;q<4;q++)
        #pragma unroll
        for(int j=0;j<8;j++) acc[q][j] = make_float2(0.f,0.f);

    for(int k0=0;k0<K;k0+=8){
        #pragma unroll
        for(int t=0;t<4;t++){
            int i = t*256+tid; int r = i>>3, kk = i&7;
            int gr = bm+r;
            As[kk][r] = (gr<Mr) ? A[(size_t)gr*lda + k0+kk] : 0.f;
        }
        #pragma unroll
        for(int t=0;t<4;t++){
            int i = t*256+tid; int kk = i>>7, c = i&127;
            int gc = bn+c;
            Bs[kk][c] = (gc<Nc) ? B[(size_t)(k0+kk)*ldb + gc] : 0.f;
        }
        __syncthreads();
        #pragma unroll
        for(int kk=0;kk<8;kk++){
            float4 a0 = *(const float4*)&As[kk][ty*8];
            float4 a1 = *(const float4*)&As[kk][ty*8+4];
            float4 b0 = *(const float4*)&Bs[kk][tx*8];
            float4 b1 = *(const float4*)&Bs[kk][tx*8+4];
            float2 a2[4] = {{a0.x,a0.y},{a0.z,a0.w},{a1.x,a1.y},{a1.z,a1.w}};
            float  rb[8] = {b0.x,b0.y,b0.z,b0.w,b1.x,b1.y,b1.z,b1.w};
            #pragma unroll
            for(int q=0;q<4;q++)
                #pragma unroll
                for(int j=0;j<8;j++)
                    ffma2(acc[q][j], a2[q], make_float2(rb[j],rb[j]));
        }
        __syncthreads();
    }
    #pragma unroll
    for(int q=0;q<4;q++){
        #pragma unroll
        for(int sgn=0;sgn<2;sgn++){
            int gr = bm + ty*8 + q*2 + sgn;
            if(gr >= Mr) continue;
            #pragma unroll
            for(int j=0;j<8;j++){
                int gc = bn + tx*8 + j;
                if(gc >= Nc) continue;
                float x = sgn ? acc[q][j].y : acc[q][j].x;
                if(bias)  x += bias[gc];
                if(act)   x = silu_f(x);
                if(accum) C[(size_t)gr*ldc+gc] += x;
                else      C[(size_t)gr*ldc+gc]  = x;
            }
        }
    }
}

// ---------------- segment-sum scatters (idx_i sorted) -----------------------
__global__ void m_scatter_k(float* __restrict__ s_out,
                            const int* __restrict__ idx_i,
                            const float* __restrict__ cutoffs){
    int f  = threadIdx.x;          // 128 threads = feature dim
    int p0 = blockIdx.x*128;       // 128 consecutive edges
    float acc = 0.f; int cur = idx_i[p0];
    for(int e=0;e<128;e++){
        int p = p0+e;
        int ii = idx_i[p];
        if(ii != cur){ atomicAdd(&s_out[(size_t)cur*FD+f], acc); acc = 0.f; cur = ii; }
        acc += g_Mi[(size_t)p*FD+f] * cutoffs[p];
    }
    atomicAdd(&s_out[(size_t)cur*FD+f], acc);
}

__global__ void dv_scatter_k(const float* __restrict__ v_in, float* __restrict__ v_out,
                             const int* __restrict__ idx_i, const int* __restrict__ idx_j,
                             const float* __restrict__ cutoffs){
    int t = threadIdx.x;           // 96 threads: d = t>>5, m = t&31
    int m = t & 31, d = t >> 5;
    int p0 = blockIdx.x*128;
    float acc = 0.f; int cur = idx_i[p0];
    for(int e=0;e<128;e++){
        int p = p0+e;
        int ii = idx_i[p];
        if(ii != cur){ atomicAdd(&v_out[(size_t)cur*96+t], acc); acc = 0.f; cur = ii; }
        int j = idx_j[p];
        float g0 = g_G[(size_t)p*64 + m];
        float g1 = g_G[(size_t)p*64 + 32 + m];
        float vj = v_in[(size_t)j*96 + t];
        acc += (g0*g_u[p*3+d] + g1*vj) * cutoffs[p];
    }
    atomicAdd(&v_out[(size_t)cur*96+t], acc);
}

__global__ void copy_s_to_h_k(const float* __restrict__ s){
    int idx = blockIdx.x*blockDim.x + threadIdx.x;
    if(idx >= NA*FD) return;
    g_hbuf[(idx/FD)*2*FD + (idx%FD)] = s[idx];
}

// ---------------- launch ----------------------------------------------------
extern "C" void kernel_launch(void* const* d_in, const int* in_sizes, int n_in,
                              void* d_out, int out_size)
{
    const float* features = (const float*)d_in[0];
    const float* distances= (const float*)d_in[1];
    const float* vectors  = (const float*)d_in[2];
    const float* cutoffs  = (const float*)d_in[3];
    const float* rbfs     = (const float*)d_in[4];
    const int*   idx_i    = (const int*)  d_in[5];
    const int*   idx_j    = (const int*)  d_in[6];
    const float* Wrbf     = (const float*)d_in[7];
    const float* Wemb     = (const float*)d_in[8];
    const float* eq0_W1   = (const float*)d_in[9];
    const float* eq0_b1   = (const float*)d_in[10];
    const float* eq0_W2   = (const float*)d_in[11];
    const float* eq1_W1   = (const float*)d_in[12];
    const float* eq1_b1   = (const float*)d_in[13];
    const float* eq1_W2   = (const float*)d_in[14];
    const float* inv_W1   = (const float*)d_in[15];
    const float* inv_b1   = (const float*)d_in[16];
    const float* inv_W2   = (const float*)d_in[17];
    const float* inv_b2   = (const float*)d_in[18];
    const float* upd_W1   = (const float*)d_in[19];
    const float* upd_b1   = (const float*)d_in[20];
    const float* upd_W2   = (const float*)d_in[21];
    const float* upd_b2   = (const float*)d_in[22];

    float* out_s = (float*)d_out;
    float* out_v = out_s + (size_t)NA*FD;

    float *pX,*pH,*pG,*pMi,*pv0,*pv1,*pW1,*pb1,*ph,*pt;
    cudaGetSymbolAddress((void**)&pX,  g_X);
    cudaGetSymbolAddress((void**)&pH,  g_H);
    cudaGetSymbolAddress((void**)&pG,  g_G);
    cudaGetSymbolAddress((void**)&pMi, g_Mi);
    cudaGetSymbolAddress((void**)&pv0, g_v0);
    cudaGetSymbolAddress((void**)&pv1, g_v1);
    cudaGetSymbolAddress((void**)&pW1, g_W1eff);
    cudaGetSymbolAddress((void**)&pb1, g_b1c);
    cudaGetSymbolAddress((void**)&ph,  g_hbuf);
    cudaGetSymbolAddress((void**)&pt,  g_tbuf);

    // init: s = features, v = 0
    cudaMemcpyAsync(out_s, features, (size_t)NA*FD*sizeof(float), cudaMemcpyDeviceToDevice, 0);
    cudaMemsetAsync(pv0, 0, (size_t)NA*96*sizeof(float), 0);
    prep_u_k<<<(PE*3+255)/256, 256>>>(vectors, distances);

    for(int b=0;b<2;b++){
        const float* eqW1 = b ? eq1_W1 : eq0_W1;
        const float* eqb1 = b ? eq1_b1 : eq0_b1;
        const float* eqW2 = b ? eq1_W2 : eq0_W2;
        float* v_in  = b ? pv1  : pv0;
        float* v_out = b ? out_v: pv1;

        prep_w1_k<<<(DX*DH+255)/256, 256>>>(b, Wrbf, eqW1, eqb1, inv_W1, inv_b1);
        edge_x_k<<<PE/4, dim3(32,4)>>>(out_s, v_in, rbfs, idx_i, idx_j);

        // H = silu(X @ W1eff + b1)    (P,480)@(480,256)
        { dim3 g(DH/128, PE/128);
          sgemm_k<<<g,256>>>(pX, DX, pW1, DH, pb1, pH, DH, PE, DH, DX, 1, 0); }
        // G = H_eq @ eqW2             (P,128)@(128,64)
        { dim3 g(1, PE/128);
          sgemm_k<<<g,256>>>(pH, DH, eqW2, 64, nullptr, pG, 64, PE, 64, FD, 0, 0); }
        // Mi = silu(H_inv @ invW2 + invb2)  (P,128)@(128,128)
        { dim3 g(1, PE/128);
          sgemm_k<<<g,256>>>(pH+FD, DH, inv_W2 + (size_t)b*FD*FD, FD,
                             inv_b2 + b*FD, pMi, FD, PE, FD, FD, 1, 0); }

        // v_out = v_in + segment_sum(dv)
        cudaMemcpyAsync(v_out, v_in, (size_t)NA*96*sizeof(float), cudaMemcpyDeviceToDevice, 0);
        dv_scatter_k<<<PE/128, 96>>>(v_in, v_out, idx_i, idx_j, cutoffs);
        // s += segment_sum(m)
        m_scatter_k<<<PE/128, 128>>>(out_s, idx_i, cutoffs);

        // node update: h = [s, s@Wemb]; s += silu(silu(h@U1+b1)@U2+b2)
        copy_s_to_h_k<<<(NA*FD+255)/256, 256>>>(out_s);
        { dim3 g(1, (NA+127)/128);
          sgemm_k<<<g,256>>>(out_s, FD, Wemb, FD, nullptr, ph+FD, 2*FD, NA, FD, FD, 0, 0); }
        { dim3 g(1, (NA+127)/128);
          sgemm_k<<<g,256>>>(ph, 2*FD, upd_W1 + (size_t)b*2*FD*FD, FD,
                             upd_b1 + b*FD, pt, FD, NA, FD, 2*FD, 1, 0); }
        { dim3 g(1, (NA+127)/128);
          sgemm_k<<<g,256>>>(pt, FD, upd_W2 + (size_t)b*FD*FD, FD,
                             upd_b2 + b*FD, out_s, FD, NA, FD, FD, 1, 1); }
    }
    (void)in_sizes; (void)n_in; (void)out_size;
}

// round 3
// speedup vs baseline: 1.7772x; 1.7760x over previous
#include <cuda_runtime.h>
#include <cuda_bf16.h>
#include <math.h>

#define NA 20000
#define PE 320000
#define FD 128
#define RD 64
#define DX 480
#define DH 256
#define DG 192

// ---------------- scratch (device globals; no allocation allowed) ----------
__device__ float g_u [PE*3];
__device__ float g_X [(size_t)PE*DX];   // [rbf 0:64 | a_* 64:224 | si 224:352 | sj 352:480]
__device__ float g_H [(size_t)PE*DH];   // [eq hidden 0:128 | inv hidden 128:256]
__device__ float g_GM[(size_t)PE*DG];   // [g0 0:32 | g1 32:64 | Mi 64:192]
__device__ float g_v0[NA*96];
__device__ float g_v1[NA*96];
__device__ float g_b1c[DH];
__device__ float g_b2c[DG];
__device__ float g_tbuf[NA*FD];
__device__ __align__(16) unsigned short g_Bh[DH*DX];  // n-major split-hi
__device__ __align__(16) unsigned short g_Bl[DH*DX];  // n-major split-lo

__device__ __forceinline__ float silu_f(float x){ return x/(1.f+__expf(-x)); }

__device__ __forceinline__ void split1(float x, unsigned short &h, unsigned short &l){
    __nv_bfloat16 hb = __float2bfloat16(x);
    float r = x - __bfloat162float(hb);
    __nv_bfloat16 lb = __float2bfloat16(r);
    h = *reinterpret_cast<unsigned short*>(&hb);
    l = *reinterpret_cast<unsigned short*>(&lb);
}
__device__ __forceinline__ void split2(float x, float y, unsigned &h, unsigned &l){
    __nv_bfloat162 hb = __floats2bfloat162_rn(x, y);
    float rx = x - __bfloat162float(hb.x);
    float ry = y - __bfloat162float(hb.y);
    __nv_bfloat162 lb = __floats2bfloat162_rn(rx, ry);
    h = *reinterpret_cast<unsigned*>(&hb);
    l = *reinterpret_cast<unsigned*>(&lb);
}

__device__ __forceinline__ void mma_bf16(float* c, unsigned a0,unsigned a1,unsigned a2,unsigned a3,
                                         unsigned b0, unsigned b1){
    asm volatile("mma.sync.aligned.m16n8k16.row.col.f32.bf16.bf16.f32 "
        "{%0,%1,%2,%3}, {%4,%5,%6,%7}, {%8,%9}, {%0,%1,%2,%3};"
        : "+f"(c[0]), "+f"(c[1]), "+f"(c[2]), "+f"(c[3])
        : "r"(a0),"r"(a1),"r"(a2),"r"(a3),"r"(b0),"r"(b1));
}
__device__ __forceinline__ void ldsm_x4(unsigned &r0,unsigned &r1,unsigned &r2,unsigned &r3, const void* p){
    unsigned addr = (unsigned)__cvta_generic_to_shared(p);
    asm volatile("ldmatrix.sync.aligned.m8n8.x4.shared.b16 {%0,%1,%2,%3}, [%4];"
        : "=r"(r0),"=r"(r1),"=r"(r2),"=r"(r3) : "r"(addr));
}

// ---------------- small prep kernels ---------------------------------------
__global__ void prep_u_k(const float* __restrict__ vectors, const float* __restrict__ dist){
    int idx = blockIdx.x*blockDim.x + threadIdx.x;
    if(idx >= PE*3) return;
    g_u[idx] = vectors[idx] / (dist[idx/3] + 0.001f);
}

// W1eff (480x256) with Wrbf folded; stored split bf16 n-major (rows=N, cols=K=480)
__global__ void prep_w1split_k(int b, const float* __restrict__ Wrbf,
                          const float* __restrict__ eqW1, const float* __restrict__ eqb1,
                          const float* __restrict__ invW1all, const float* __restrict__ invb1all){
    int idx = blockIdx.x*blockDim.x + threadIdx.x;
    if(idx >= DX*DH) return;
    int r = idx / DH, c = idx % DH;
    bool inv = (c >= FD);
    int cc = c & (FD-1);
    const float* W1 = inv ? (invW1all + (size_t)b*448*FD) : eqW1;
    float acc = 0.f;
    if(r < 64){
        #pragma unroll 8
        for(int k=0;k<32;k++) acc += Wrbf[r*32+k]*W1[k*FD+cc];
    } else if(r < 224){
        int ar = r-64;
        if(inv || b==1) acc = W1[(32+ar)*FD+cc];
    } else if(r < 352){
        int sr = r-224;
        int baseRow = (inv || b==1) ? (192+sr) : (32+sr);
        acc = W1[baseRow*FD+cc];
        #pragma unroll 8
        for(int k=0;k<32;k++) acc += Wrbf[(64+sr)*32+k]*W1[k*FD+cc];
    } else {
        int jr = r-352;
        int baseRow = (inv || b==1) ? (320+jr) : (160+jr);
        acc = W1[baseRow*FD+cc];
        #pragma unroll 8
        for(int k=0;k<32;k++) acc += Wrbf[(192+jr)*32+k]*W1[k*FD+cc];
    }
    unsigned short h,l; split1(acc,h,l);
    g_Bh[(size_t)c*DX + r] = h;
    g_Bl[(size_t)c*DX + r] = l;
    if(r==0) g_b1c[c] = inv ? invb1all[b*FD+cc] : eqb1[cc];
}

// W2eff (256x192) block-diagonal [eqW2 | invW2]; split n-major (K=256)
__global__ void prep_w2split_k(int b, const float* __restrict__ eqW2,
                               const float* __restrict__ invW2all, const float* __restrict__ invb2all){
    int idx = blockIdx.x*blockDim.x + threadIdx.x;
    if(idx >= DG*DH) return;
    int c = idx / DH, r = idx % DH;
    float val = 0.f;
    if(c < 64){ if(r < FD)  val = eqW2[r*64 + c]; }
    else      { if(r >= FD) val = invW2all[(size_t)b*FD*FD + (r-FD)*FD + (c-64)]; }
    unsigned short h,l; split1(val,h,l);
    g_Bh[(size_t)c*DH + r] = h;
    g_Bl[(size_t)c*DH + r] = l;
    if(r==0) g_b2c[c] = (c>=64) ? invb2all[b*FD + (c-64)] : 0.f;
}

// W1u = U1_top + Wemb @ U1_bot  (128x128); split n-major (K=128)
__global__ void prep_u1split_k(const float* __restrict__ U1, const float* __restrict__ Wemb){
    int idx = blockIdx.x*blockDim.x + threadIdx.x;
    if(idx >= FD*FD) return;
    int c = idx / FD, r = idx % FD;
    float val = U1[r*FD + c];
    #pragma unroll 8
    for(int k=0;k<FD;k++) val += Wemb[r*FD + k] * U1[(FD+k)*FD + c];
    unsigned short h,l; split1(val,h,l);
    g_Bh[(size_t)c*FD + r] = h;
    g_Bl[(size_t)c*FD + r] = l;
}

__global__ void prep_u2split_k(const float* __restrict__ U2){
    int idx = blockIdx.x*blockDim.x + threadIdx.x;
    if(idx >= FD*FD) return;
    int c = idx / FD, r = idx % FD;
    unsigned short h,l; split1(U2[r*FD + c],h,l);
    g_Bh[(size_t)c*FD + r] = h;
    g_Bl[(size_t)c*FD + r] = l;
}

// Per-edge feature row
__global__ void edge_x_k(const float* __restrict__ s, const float* __restrict__ v_in,
                         const float* __restrict__ rbfs,
                         const int* __restrict__ idx_i, const int* __restrict__ idx_j){
    int p = blockIdx.x*4 + threadIdx.y;
    int lane = threadIdx.x;
    int i = idx_i[p], j = idx_j[p];
    float* xr = g_X + (size_t)p*DX;
    for(int t=lane;t<RD;t+=32) xr[t] = rbfs[(size_t)p*RD+t];
    float u0 = g_u[p*3+0], u1 = g_u[p*3+1], u2 = g_u[p*3+2];
    const float* vi  = v_in + (size_t)i*96;
    const float* vjp = v_in + (size_t)j*96;
    float vi0=vi[lane],  vi1=vi[32+lane],  vi2=vi[64+lane];
    float vj0=vjp[lane], vj1=vjp[32+lane], vj2=vjp[64+lane];
    xr[ 64+lane] = u0*vi0 + u1*vi1 + u2*vi2;
    xr[ 96+lane] = u0*vj0 + u1*vj1 + u2*vj2;
    xr[128+lane] = vi0*vj0 + vi1*vj1 + vi2*vj2;
    xr[160+lane] = vi0*vi0 + vi1*vi1 + vi2*vi2;
    xr[192+lane] = vj0*vj0 + vj1*vj1 + vj2*vj2;
    const float* si = s + (size_t)i*FD;
    const float* sj = s + (size_t)j*FD;
    for(int t=lane;t<FD;t+=32){ xr[224+t]=si[t]; xr[352+t]=sj[t]; }
}

// ---------------- bf16x3 tensor-core GEMM ----------------------------------
// C = [accum +] f(A@B + bias); silu+bias applied only for cols >= act_start.
// A fp32 row-major (M,K); Bh/Bl pre-split bf16, n-major (N rows of K).
__global__ __launch_bounds__(256) void gemm_k(
    const float* __restrict__ A, int lda,
    const unsigned short* __restrict__ Bh, const unsigned short* __restrict__ Bl,
    const float* __restrict__ bias,
    float* __restrict__ C, int ldc,
    int M, int N, int K, int act_start, int accum)
{
    __shared__ unsigned As[2][128][20];   // cols 0-7: hi k-pairs, 8-15: lo, pad->20
    __shared__ unsigned Bs[2][128][20];
    const int tid = threadIdx.x;
    const int lane = tid & 31, w = tid >> 5;
    const int wm = (w >> 2) * 64, wn = (w & 3) * 32;
    const int g = lane >> 2, tig = lane & 3;
    const int bm = blockIdx.y * 128, bn = blockIdx.x * 128;

    const int ar = tid >> 1;
    const int ak = (tid & 1) * 8;     // k-element offset within stage
    const int kc = ak >> 1;           // uint-pair offset
    const bool aok = (bm + ar) < M;
    const bool bok = (bn + ar) < N;
    const float* Aptr = A + (size_t)(bm+ar)*lda + ak;
    const unsigned short* Bhp = Bh + (size_t)(bn+ar)*K + ak;
    const unsigned short* Blp = Bl + (size_t)(bn+ar)*K + ak;

    float acc[4][4][4];
    #pragma unroll
    for(int i=0;i<4;i++)
        #pragma unroll
        for(int j=0;j<4;j++)
            #pragma unroll
            for(int q=0;q<4;q++) acc[i][j][q]=0.f;

    float4 a0v, a1v; uint4 bhv, blv;
    a0v = aok ? *(const float4*)(Aptr)   : make_float4(0,0,0,0);
    a1v = aok ? *(const float4*)(Aptr+4) : make_float4(0,0,0,0);
    bhv = bok ? *(const uint4*)(Bhp) : make_uint4(0,0,0,0);
    blv = bok ? *(const uint4*)(Blp) : make_uint4(0,0,0,0);

    const int nstage = K >> 4;
    for(int t=0; t<nstage; t++){
        const int cur = t & 1;
        {
            unsigned h0,l0,h1,l1,h2,l2,h3,l3;
            split2(a0v.x,a0v.y,h0,l0); split2(a0v.z,a0v.w,h1,l1);
            split2(a1v.x,a1v.y,h2,l2); split2(a1v.z,a1v.w,h3,l3);
            *(uint4*)&As[cur][ar][kc]   = make_uint4(h0,h1,h2,h3);
            *(uint4*)&As[cur][ar][8+kc] = make_uint4(l0,l1,l2,l3);
            *(uint4*)&Bs[cur][ar][kc]   = bhv;
            *(uint4*)&Bs[cur][ar][8+kc] = blv;
        }
        __syncthreads();
        if(t+1 < nstage){
            const int k0 = (t+1)*16;
            a0v = aok ? *(const float4*)(Aptr + k0)     : make_float4(0,0,0,0);
            a1v = aok ? *(const float4*)(Aptr + k0 + 4) : make_float4(0,0,0,0);
            bhv = bok ? *(const uint4*)(Bhp + k0) : make_uint4(0,0,0,0);
            blv = bok ? *(const uint4*)(Blp + k0) : make_uint4(0,0,0,0);
        }
        unsigned bf[4][4];
        #pragma unroll
        for(int nt=0;nt<4;nt++){
            const unsigned* bp = &Bs[cur][wn + nt*8 + g][0];
            bf[nt][0]=bp[tig];   bf[nt][1]=bp[tig+4];
            bf[nt][2]=bp[8+tig]; bf[nt][3]=bp[8+tig+4];
        }
        #pragma unroll
        for(int mt=0;mt<4;mt++){
            unsigned ah0,ah1,ah2,ah3, al0,al1,al2,al3;
            const int row = wm + mt*16 + (lane & 15);
            const int kq  = (lane >> 4) * 4;
            ldsm_x4(ah0,ah1,ah2,ah3, &As[cur][row][kq]);
            ldsm_x4(al0,al1,al2,al3, &As[cur][row][8+kq]);
            #pragma unroll
            for(int nt=0;nt<4;nt++){
                mma_bf16(acc[mt][nt], ah0,ah1,ah2,ah3, bf[nt][0], bf[nt][1]);
                mma_bf16(acc[mt][nt], al0,al1,al2,al3, bf[nt][0], bf[nt][1]);
                mma_bf16(acc[mt][nt], ah0,ah1,ah2,ah3, bf[nt][2], bf[nt][3]);
            }
        }
        __syncthreads();
    }

    #pragma unroll
    for(int mt=0;mt<4;mt++){
        #pragma unroll
        for(int nt=0;nt<4;nt++){
            const int r0 = bm + wm + mt*16 + g;
            const int c0 = bn + wn + nt*8 + 2*tig;
            if(c0 >= N) continue;
            float x0=acc[mt][nt][0], x1=acc[mt][nt][1], x2=acc[mt][nt][2], x3=acc[mt][nt][3];
            if(c0 >= act_start){
                float bb0 = bias[c0], bb1 = bias[c0+1];
                x0 = silu_f(x0+bb0); x1 = silu_f(x1+bb1);
                x2 = silu_f(x2+bb0); x3 = silu_f(x3+bb1);
            }
            if(r0 < M){
                float2* o = (float2*)&C[(size_t)r0*ldc + c0];
                if(accum){ float2 p=*o; *o = make_float2(p.x+x0, p.y+x1); }
                else      *o = make_float2(x0, x1);
            }
            if(r0+8 < M){
                float2* o = (float2*)&C[(size_t)(r0+8)*ldc + c0];
                if(accum){ float2 p=*o; *o = make_float2(p.x+x2, p.y+x3); }
                else      *o = make_float2(x2, x3);
            }
        }
    }
}

// ---------------- segment-sum scatters (idx_i sorted) -----------------------
__global__ void m_scatter_k(float* __restrict__ s_out,
                            const int* __restrict__ idx_i,
                            const float* __restrict__ cutoffs){
    int f  = threadIdx.x;
    int p0 = blockIdx.x*128;
    float acc = 0.f; int cur = idx_i[p0];
    for(int e=0;e<128;e++){
        int p = p0+e;
        int ii = idx_i[p];
        if(ii != cur){ atomicAdd(&s_out[(size_t)cur*FD+f], acc); acc = 0.f; cur = ii; }
        acc += g_GM[(size_t)p*DG + 64 + f] * cutoffs[p];
    }
    atomicAdd(&s_out[(size_t)cur*FD+f], acc);
}

__global__ void dv_scatter_k(const float* __restrict__ v_in, float* __restrict__ v_out,
                             const int* __restrict__ idx_i, const int* __restrict__ idx_j,
                             const float* __restrict__ cutoffs){
    int t = threadIdx.x;
    int m = t & 31, d = t >> 5;
    int p0 = blockIdx.x*128;
    float acc = 0.f; int cur = idx_i[p0];
    for(int e=0;e<128;e++){
        int p = p0+e;
        int ii = idx_i[p];
        if(ii != cur){ atomicAdd(&v_out[(size_t)cur*96+t], acc); acc = 0.f; cur = ii; }
        int j = idx_j[p];
        float g0 = g_GM[(size_t)p*DG + m];
        float g1 = g_GM[(size_t)p*DG + 32 + m];
        float vj = v_in[(size_t)j*96 + t];
        acc += (g0*g_u[p*3+d] + g1*vj) * cutoffs[p];
    }
    atomicAdd(&v_out[(size_t)cur*96+t], acc);
}

// ---------------- launch ----------------------------------------------------
extern "C" void kernel_launch(void* const* d_in, const int* in_sizes, int n_in,
                              void* d_out, int out_size)
{
    const float* features = (const float*)d_in[0];
    const float* distances= (const float*)d_in[1];
    const float* vectors  = (const float*)d_in[2];
    const float* cutoffs  = (const float*)d_in[3];
    const float* rbfs     = (const float*)d_in[4];
    const int*   idx_i    = (const int*)  d_in[5];
    const int*   idx_j    = (const int*)  d_in[6];
    const float* Wrbf     = (const float*)d_in[7];
    const float* Wemb     = (const float*)d_in[8];
    const float* eq0_W1   = (const float*)d_in[9];
    const float* eq0_b1   = (const float*)d_in[10];
    const float* eq0_W2   = (const float*)d_in[11];
    const float* eq1_W1   = (const float*)d_in[12];
    const float* eq1_b1   = (const float*)d_in[13];
    const float* eq1_W2   = (const float*)d_in[14];
    const float* inv_W1   = (const float*)d_in[15];
    const float* inv_b1   = (const float*)d_in[16];
    const float* inv_W2   = (const float*)d_in[17];
    const float* inv_b2   = (const float*)d_in[18];
    const float* upd_W1   = (const float*)d_in[19];
    const float* upd_b1   = (const float*)d_in[20];
    const float* upd_W2   = (const float*)d_in[21];
    const float* upd_b2   = (const float*)d_in[22];

    float* out_s = (float*)d_out;
    float* out_v = out_s + (size_t)NA*FD;

    float *pX,*pH,*pGM,*pv0,*pv1,*pb1,*pb2,*pt;
    unsigned short *pBh,*pBl;
    cudaGetSymbolAddress((void**)&pX,  g_X);
    cudaGetSymbolAddress((void**)&pH,  g_H);
    cudaGetSymbolAddress((void**)&pGM, g_GM);
    cudaGetSymbolAddress((void**)&pv0, g_v0);
    cudaGetSymbolAddress((void**)&pv1, g_v1);
    cudaGetSymbolAddress((void**)&pb1, g_b1c);
    cudaGetSymbolAddress((void**)&pb2, g_b2c);
    cudaGetSymbolAddress((void**)&pt,  g_tbuf);
    cudaGetSymbolAddress((void**)&pBh, g_Bh);
    cudaGetSymbolAddress((void**)&pBl, g_Bl);

    // init: s = features, v = 0
    cudaMemcpyAsync(out_s, features, (size_t)NA*FD*sizeof(float), cudaMemcpyDeviceToDevice, 0);
    cudaMemsetAsync(pv0, 0, (size_t)NA*96*sizeof(float), 0);
    prep_u_k<<<(PE*3+255)/256, 256>>>(vectors, distances);

    for(int b=0;b<2;b++){
        const float* eqW1 = b ? eq1_W1 : eq0_W1;
        const float* eqb1 = b ? eq1_b1 : eq0_b1;
        const float* eqW2 = b ? eq1_W2 : eq0_W2;
        float* v_in  = b ? pv1  : pv0;
        float* v_out = b ? out_v: pv1;

        prep_w1split_k<<<(DX*DH+255)/256, 256>>>(b, Wrbf, eqW1, eqb1, inv_W1, inv_b1);
        edge_x_k<<<PE/4, dim3(32,4)>>>(out_s, v_in, rbfs, idx_i, idx_j);

        // H = silu(X @ W1eff + b1)    (P,480)@(480,256)
        { dim3 g(2, PE/128);
          gemm_k<<<g,256>>>(pX, DX, pBh, pBl, pb1, pH, DH, PE, DH, DX, 0, 0); }

        prep_w2split_k<<<(DG*DH+255)/256, 256>>>(b, eqW2, inv_W2, inv_b2);
        // [G | Mi] = H @ W2eff (block-diag); silu+bias only on Mi cols (>=64)
        { dim3 g(2, PE/128);
          gemm_k<<<g,256>>>(pH, DH, pBh, pBl, pb2, pGM, DG, PE, DG, DH, 64, 0); }

        // v_out = v_in + segment_sum(dv)
        cudaMemcpyAsync(v_out, v_in, (size_t)NA*96*sizeof(float), cudaMemcpyDeviceToDevice, 0);
        dv_scatter_k<<<PE/128, 96>>>(v_in, v_out, idx_i, idx_j, cutoffs);
        // s += segment_sum(m)
        m_scatter_k<<<PE/128, 128>>>(out_s, idx_i, cutoffs);

        // node update with Wemb folded into U1: t = silu(s@W1u + b1u)
        prep_u1split_k<<<(FD*FD+255)/256, 256>>>(upd_W1 + (size_t)b*2*FD*FD, Wemb);
        { dim3 g(1, (NA+127)/128);
          gemm_k<<<g,256>>>(out_s, FD, pBh, pBl, upd_b1 + b*FD, pt, FD, NA, FD, FD, 0, 0); }
        prep_u2split_k<<<(FD*FD+255)/256, 256>>>(upd_W2 + (size_t)b*FD*FD);
        // s += silu(t@U2 + b2u)
        { dim3 g(1, (NA+127)/128);
          gemm_k<<<g,256>>>(pt, FD, pBh, pBl, upd_b2 + b*FD, out_s, FD, NA, FD, FD, 0, 1); }
    }
    (void)in_sizes; (void)n_in; (void)out_size;
}

// round 4
// speedup vs baseline: 4.0034x; 2.2527x over previous
#include <cuda_runtime.h>
#include <cuda_bf16.h>
#include <math.h>

#define NA 20000
#define PE 320000
#define FD 128
#define RD 64
#define DH 256
#define DG 192
#define KA 160      // a_* columns
#define KW1 224     // rbf(64) + a(160)
#define YW 512
#define NOACT (1<<30)

// ---------------- scratch (device globals; no allocation allowed) ----------
__device__ float g_u [PE*3];
__device__ float g_X [(size_t)PE*KA];   // a_* only (block 1)
__device__ float g_H [(size_t)PE*DH];   // [eq hidden 0:128 | inv hidden 128:256]
__device__ float g_GM[(size_t)PE*DG];   // [g0 0:32 | g1 32:64 | Mi 64:192]
__device__ float g_Y [(size_t)NA*YW];   // [Yi 0:256 | Yj 256:512]
__device__ float g_v0[NA*96];
__device__ float g_v1[NA*96];
__device__ float g_b1c[DH];
__device__ float g_tbuf[NA*FD];
__device__ __align__(16) unsigned short g_Bh[YW*FD > DH*KW1 ? YW*FD : DH*KW1];
__device__ __align__(16) unsigned short g_Bl[YW*FD > DH*KW1 ? YW*FD : DH*KW1];

__device__ __forceinline__ float silu_f(float x){ return x/(1.f+__expf(-x)); }

__device__ __forceinline__ void split1(float x, unsigned short &h, unsigned short &l){
    __nv_bfloat16 hb = __float2bfloat16(x);
    float r = x - __bfloat162float(hb);
    __nv_bfloat16 lb = __float2bfloat16(r);
    h = *reinterpret_cast<unsigned short*>(&hb);
    l = *reinterpret_cast<unsigned short*>(&lb);
}
__device__ __forceinline__ void split2(float x, float y, unsigned &h, unsigned &l){
    __nv_bfloat162 hb = __floats2bfloat162_rn(x, y);
    float rx = x - __bfloat162float(hb.x);
    float ry = y - __bfloat162float(hb.y);
    __nv_bfloat162 lb = __floats2bfloat162_rn(rx, ry);
    h = *reinterpret_cast<unsigned*>(&hb);
    l = *reinterpret_cast<unsigned*>(&lb);
}

__device__ __forceinline__ void mma_bf16(float* c, unsigned a0,unsigned a1,unsigned a2,unsigned a3,
                                         unsigned b0, unsigned b1){
    asm volatile("mma.sync.aligned.m16n8k16.row.col.f32.bf16.bf16.f32 "
        "{%0,%1,%2,%3}, {%4,%5,%6,%7}, {%8,%9}, {%0,%1,%2,%3};"
        : "+f"(c[0]), "+f"(c[1]), "+f"(c[2]), "+f"(c[3])
        : "r"(a0),"r"(a1),"r"(a2),"r"(a3),"r"(b0),"r"(b1));
}
__device__ __forceinline__ void ldsm_x4(unsigned &r0,unsigned &r1,unsigned &r2,unsigned &r3, const void* p){
    unsigned addr = (unsigned)__cvta_generic_to_shared(p);
    asm volatile("ldmatrix.sync.aligned.m8n8.x4.shared.b16 {%0,%1,%2,%3}, [%4];"
        : "=r"(r0),"=r"(r1),"=r"(r2),"=r"(r3) : "r"(addr));
}

// ---------------- small prep kernels ---------------------------------------
__global__ void prep_u_k(const float* __restrict__ vectors, const float* __restrict__ dist){
    int idx = blockIdx.x*blockDim.x + threadIdx.x;
    if(idx >= PE*3) return;
    g_u[idx] = vectors[idx] / (dist[idx/3] + 0.001f);
}

// Wy (K=128 -> N=512): node-side weights [W1i_eff | W1j_eff] with Wrbf folded.
__global__ void prep_wy_k(int b, const float* __restrict__ Wrbf,
                          const float* __restrict__ eqW1,
                          const float* __restrict__ invW1all){
    int idx = blockIdx.x*blockDim.x + threadIdx.x;
    if(idx >= YW*FD) return;
    int c = idx / FD, r = idx % FD;
    int sj = c >> 8;                 // 0: si, 1: sj
    int cpack = c & 255;
    bool inv = (cpack >= FD);
    int cc = cpack & (FD-1);
    const float* W1 = inv ? (invW1all + (size_t)b*448*FD) : eqW1;
    int base;
    if(sj == 0) base = (inv || b==1) ? 192 : 32;
    else        base = (inv || b==1) ? 320 : 160;
    float val = W1[(base + r)*FD + cc];
    int wr = (sj ? 192 : 64) + r;    // Wrbf row for this feature
    #pragma unroll 8
    for(int k=0;k<32;k++) val += Wrbf[wr*32+k]*W1[k*FD+cc];
    unsigned short h,l; split1(val,h,l);
    g_Bh[(size_t)c*FD + r] = h;
    g_Bl[(size_t)c*FD + r] = l;
}

// W1 edge part (KW x 256): rows 0:64 rbf-fold, rows 64:224 a_* (block1 only)
__global__ void prep_w1split_k(int b, int KW, const float* __restrict__ Wrbf,
                          const float* __restrict__ eqW1, const float* __restrict__ eqb1,
                          const float* __restrict__ invW1all, const float* __restrict__ invb1all){
    int idx = blockIdx.x*blockDim.x + threadIdx.x;
    if(idx >= KW*DH) return;
    int r = idx / DH, c = idx % DH;
    bool inv = (c >= FD);
    int cc = c & (FD-1);
    const float* W1 = inv ? (invW1all + (size_t)b*448*FD) : eqW1;
    float acc = 0.f;
    if(r < 64){
        #pragma unroll 8
        for(int k=0;k<32;k++) acc += Wrbf[r*32+k]*W1[k*FD+cc];
    } else {
        int ar = r-64;
        if(inv || b==1) acc = W1[(32+ar)*FD+cc];
    }
    unsigned short h,l; split1(acc,h,l);
    g_Bh[(size_t)c*KW + r] = h;
    g_Bl[(size_t)c*KW + r] = l;
    if(r==0) g_b1c[c] = inv ? invb1all[b*FD+cc] : eqb1[cc];
}

// eqW2 (128x64) -> n-major split
__global__ void prep_w2g_k(const float* __restrict__ eqW2){
    int idx = blockIdx.x*blockDim.x + threadIdx.x;
    if(idx >= 64*FD) return;
    int c = idx / FD, r = idx % FD;
    unsigned short h,l; split1(eqW2[r*64 + c],h,l);
    g_Bh[(size_t)c*FD + r] = h;
    g_Bl[(size_t)c*FD + r] = l;
}
// invW2 (128x128) -> n-major split
__global__ void prep_w2m_k(int b, const float* __restrict__ invW2all){
    int idx = blockIdx.x*blockDim.x + threadIdx.x;
    if(idx >= FD*FD) return;
    int c = idx / FD, r = idx % FD;
    unsigned short h,l; split1(invW2all[(size_t)b*FD*FD + r*FD + c],h,l);
    g_Bh[(size_t)c*FD + r] = h;
    g_Bl[(size_t)c*FD + r] = l;
}
// W1u = U1_top + Wemb @ U1_bot (128x128)
__global__ void prep_u1split_k(const float* __restrict__ U1, const float* __restrict__ Wemb){
    int idx = blockIdx.x*blockDim.x + threadIdx.x;
    if(idx >= FD*FD) return;
    int c = idx / FD, r = idx % FD;
    float val = U1[r*FD + c];
    #pragma unroll 8
    for(int k=0;k<FD;k++) val += Wemb[r*FD + k] * U1[(FD+k)*FD + c];
    unsigned short h,l; split1(val,h,l);
    g_Bh[(size_t)c*FD + r] = h;
    g_Bl[(size_t)c*FD + r] = l;
}
__global__ void prep_u2split_k(const float* __restrict__ U2){
    int idx = blockIdx.x*blockDim.x + threadIdx.x;
    if(idx >= FD*FD) return;
    int c = idx / FD, r = idx % FD;
    unsigned short h,l; split1(U2[r*FD + c],h,l);
    g_Bh[(size_t)c*FD + r] = h;
    g_Bl[(size_t)c*FD + r] = l;
}

// Per-edge a_* row (block 1 only): [a_ui a_uj a_ij a_ii a_jj] x 32
__global__ void edge_x_k(const float* __restrict__ v_in,
                         const int* __restrict__ idx_i, const int* __restrict__ idx_j){
    int p = blockIdx.x*8 + threadIdx.y;
    int lane = threadIdx.x;
    int i = idx_i[p], j = idx_j[p];
    float* xr = g_X + (size_t)p*KA;
    float u0 = g_u[p*3+0], u1 = g_u[p*3+1], u2 = g_u[p*3+2];
    const float* vi  = v_in + (size_t)i*96;
    const float* vjp = v_in + (size_t)j*96;
    float vi0=vi[lane],  vi1=vi[32+lane],  vi2=vi[64+lane];
    float vj0=vjp[lane], vj1=vjp[32+lane], vj2=vjp[64+lane];
    xr[      lane] = u0*vi0 + u1*vi1 + u2*vi2;
    xr[ 32+lane] = u0*vj0 + u1*vj1 + u2*vj2;
    xr[ 64+lane] = vi0*vj0 + vi1*vj1 + vi2*vj2;
    xr[ 96+lane] = vi0*vi0 + vi1*vi1 + vi2*vi2;
    xr[128+lane] = vj0*vj0 + vj1*vj1 + vj2*vj2;
}

// ---------------- bf16x3 tensor-core GEMM ----------------------------------
// A = [A1 (K1 cols) | A2 (K-K1 cols)] fp32 row-major; B pre-split bf16 n-major.
// Optional epilogue gather: += Yg[gi[r]*512 + c] + Yg[gj[r]*512 + 256 + c].
// silu(x+bias) applied for cols >= act_start.
__global__ __launch_bounds__(256) void gemm_k(
    const float* __restrict__ A1, int lda1, int K1,
    const float* __restrict__ A2, int lda2,
    const unsigned short* __restrict__ Bh, const unsigned short* __restrict__ Bl,
    const float* __restrict__ bias,
    const float* __restrict__ Yg, const int* __restrict__ gi, const int* __restrict__ gj,
    float* __restrict__ C, int ldc,
    int M, int N, int K, int act_start, int accum)
{
    __shared__ unsigned As[2][128][20];
    __shared__ unsigned Bs[2][128][20];
    const int tid = threadIdx.x;
    const int lane = tid & 31, w = tid >> 5;
    const int wm = (w >> 2) * 64, wn = (w & 3) * 32;
    const int g = lane >> 2, tig = lane & 3;
    const int bm = blockIdx.y * 128, bn = blockIdx.x * 128;

    const int ar = tid >> 1;
    const int ak = (tid & 1) * 8;
    const int kc = ak >> 1;
    const int arow = bm + ar;
    const bool aok = arow < M;
    const bool bok = (bn + ar) < N;
    const unsigned short* Bhp = Bh + (size_t)(bn+ar)*K + ak;
    const unsigned short* Blp = Bl + (size_t)(bn+ar)*K + ak;

    float acc[4][4][4];
    #pragma unroll
    for(int i=0;i<4;i++)
        #pragma unroll
        for(int j=0;j<4;j++)
            #pragma unroll
            for(int q=0;q<4;q++) acc[i][j][q]=0.f;

    float4 a0v, a1v; uint4 bhv, blv;
    {
        int kk = ak;
        const float* ap = (kk < K1) ? A1 + (size_t)arow*lda1 + kk
                                    : A2 + (size_t)arow*lda2 + (kk - K1);
        a0v = aok ? *(const float4*)(ap)   : make_float4(0,0,0,0);
        a1v = aok ? *(const float4*)(ap+4) : make_float4(0,0,0,0);
    }
    bhv = bok ? *(const uint4*)(Bhp) : make_uint4(0,0,0,0);
    blv = bok ? *(const uint4*)(Blp) : make_uint4(0,0,0,0);

    const int nstage = K >> 4;
    for(int t=0; t<nstage; t++){
        const int cur = t & 1;
        {
            unsigned h0,l0,h1,l1,h2,l2,h3,l3;
            split2(a0v.x,a0v.y,h0,l0); split2(a0v.z,a0v.w,h1,l1);
            split2(a1v.x,a1v.y,h2,l2); split2(a1v.z,a1v.w,h3,l3);
            *(uint4*)&As[cur][ar][kc]   = make_uint4(h0,h1,h2,h3);
            *(uint4*)&As[cur][ar][8+kc] = make_uint4(l0,l1,l2,l3);
            *(uint4*)&Bs[cur][ar][kc]   = bhv;
            *(uint4*)&Bs[cur][ar][8+kc] = blv;
        }
        __syncthreads();
        if(t+1 < nstage){
            const int kk = (t+1)*16 + ak;
            const float* ap = (kk < K1) ? A1 + (size_t)arow*lda1 + kk
                                        : A2 + (size_t)arow*lda2 + (kk - K1);
            a0v = aok ? *(const float4*)(ap)   : make_float4(0,0,0,0);
            a1v = aok ? *(const float4*)(ap+4) : make_float4(0,0,0,0);
            bhv = bok ? *(const uint4*)(Bhp + (t+1)*16) : make_uint4(0,0,0,0);
            blv = bok ? *(const uint4*)(Blp + (t+1)*16) : make_uint4(0,0,0,0);
        }
        unsigned bf[4][4];
        #pragma unroll
        for(int nt=0;nt<4;nt++){
            const unsigned* bp = &Bs[cur][wn + nt*8 + g][0];
            bf[nt][0]=bp[tig];   bf[nt][1]=bp[tig+4];
            bf[nt][2]=bp[8+tig]; bf[nt][3]=bp[8+tig+4];
        }
        #pragma unroll
        for(int mt=0;mt<4;mt++){
            unsigned ah0,ah1,ah2,ah3, al0,al1,al2,al3;
            const int row = wm + mt*16 + (lane & 15);
            const int kq  = (lane >> 4) * 4;
            ldsm_x4(ah0,ah1,ah2,ah3, &As[cur][row][kq]);
            ldsm_x4(al0,al1,al2,al3, &As[cur][row][8+kq]);
            #pragma unroll
            for(int nt=0;nt<4;nt++){
                mma_bf16(acc[mt][nt], ah0,ah1,ah2,ah3, bf[nt][0], bf[nt][1]);
                mma_bf16(acc[mt][nt], al0,al1,al2,al3, bf[nt][0], bf[nt][1]);
                mma_bf16(acc[mt][nt], ah0,ah1,ah2,ah3, bf[nt][2], bf[nt][3]);
            }
        }
        __syncthreads();
    }

    #pragma unroll
    for(int mt=0;mt<4;mt++){
        const int r0 = bm + wm + mt*16 + g;
        const bool r0ok = r0 < M, r1ok = (r0+8) < M;
        int i0=0,j0=0,i1=0,j1=0;
        if(Yg){
            if(r0ok){ i0=gi[r0];   j0=gj[r0];   }
            if(r1ok){ i1=gi[r0+8]; j1=gj[r0+8]; }
        }
        #pragma unroll
        for(int nt=0;nt<4;nt++){
            const int c0 = bn + wn + nt*8 + 2*tig;
            if(c0 >= N) continue;
            float x0=acc[mt][nt][0], x1=acc[mt][nt][1], x2=acc[mt][nt][2], x3=acc[mt][nt][3];
            if(Yg){
                if(r0ok){
                    float2 yi = *(const float2*)&Yg[(size_t)i0*YW + c0];
                    float2 yj = *(const float2*)&Yg[(size_t)j0*YW + 256 + c0];
                    x0 += yi.x + yj.x; x1 += yi.y + yj.y;
                }
                if(r1ok){
                    float2 yi = *(const float2*)&Yg[(size_t)i1*YW + c0];
                    float2 yj = *(const float2*)&Yg[(size_t)j1*YW + 256 + c0];
                    x2 += yi.x + yj.x; x3 += yi.y + yj.y;
                }
            }
            if(c0 >= act_start){
                float bb0 = bias[c0], bb1 = bias[c0+1];
                x0 = silu_f(x0+bb0); x1 = silu_f(x1+bb1);
                x2 = silu_f(x2+bb0); x3 = silu_f(x3+bb1);
            }
            if(r0ok){
                float2* o = (float2*)&C[(size_t)r0*ldc + c0];
                if(accum){ float2 p=*o; *o = make_float2(p.x+x0, p.y+x1); }
                else      *o = make_float2(x0, x1);
            }
            if(r1ok){
                float2* o = (float2*)&C[(size_t)(r0+8)*ldc + c0];
                if(accum){ float2 p=*o; *o = make_float2(p.x+x2, p.y+x3); }
                else      *o = make_float2(x2, x3);
            }
        }
    }
}

// ---------------- segment-sum scatters (idx_i sorted) -----------------------
__global__ void m_scatter_k(float* __restrict__ s_out,
                            const int* __restrict__ idx_i,
                            const float* __restrict__ cutoffs){
    int f  = threadIdx.x;
    int p0 = blockIdx.x*128;
    float acc = 0.f; int cur = idx_i[p0];
    for(int e=0;e<128;e++){
        int p = p0+e;
        int ii = idx_i[p];
        if(ii != cur){ atomicAdd(&s_out[(size_t)cur*FD+f], acc); acc = 0.f; cur = ii; }
        acc += g_GM[(size_t)p*DG + 64 + f] * cutoffs[p];
    }
    atomicAdd(&s_out[(size_t)cur*FD+f], acc);
}

__global__ void dv_scatter_k(const float* __restrict__ v_in, float* __restrict__ v_out,
                             const int* __restrict__ idx_i, const int* __restrict__ idx_j,
                             const float* __restrict__ cutoffs){
    int t = threadIdx.x;
    int m = t & 31, d = t >> 5;
    int p0 = blockIdx.x*128;
    float acc = 0.f; int cur = idx_i[p0];
    for(int e=0;e<128;e++){
        int p = p0+e;
        int ii = idx_i[p];
        if(ii != cur){ atomicAdd(&v_out[(size_t)cur*96+t], acc); acc = 0.f; cur = ii; }
        int j = idx_j[p];
        float g0 = g_GM[(size_t)p*DG + m];
        float g1 = g_GM[(size_t)p*DG + 32 + m];
        float vj = v_in[(size_t)j*96 + t];
        acc += (g0*g_u[p*3+d] + g1*vj) * cutoffs[p];
    }
    atomicAdd(&v_out[(size_t)cur*96+t], acc);
}

// ---------------- launch ----------------------------------------------------
extern "C" void kernel_launch(void* const* d_in, const int* in_sizes, int n_in,
                              void* d_out, int out_size)
{
    const float* features = (const float*)d_in[0];
    const float* distances= (const float*)d_in[1];
    const float* vectors  = (const float*)d_in[2];
    const float* cutoffs  = (const float*)d_in[3];
    const float* rbfs     = (const float*)d_in[4];
    const int*   idx_i    = (const int*)  d_in[5];
    const int*   idx_j    = (const int*)  d_in[6];
    const float* Wrbf     = (const float*)d_in[7];
    const float* Wemb     = (const float*)d_in[8];
    const float* eq0_W1   = (const float*)d_in[9];
    const float* eq0_b1   = (const float*)d_in[10];
    const float* eq0_W2   = (const float*)d_in[11];
    const float* eq1_W1   = (const float*)d_in[12];
    const float* eq1_b1   = (const float*)d_in[13];
    const float* eq1_W2   = (const float*)d_in[14];
    const float* inv_W1   = (const float*)d_in[15];
    const float* inv_b1   = (const float*)d_in[16];
    const float* inv_W2   = (const float*)d_in[17];
    const float* inv_b2   = (const float*)d_in[18];
    const float* upd_W1   = (const float*)d_in[19];
    const float* upd_b1   = (const float*)d_in[20];
    const float* upd_W2   = (const float*)d_in[21];
    const float* upd_b2   = (const float*)d_in[22];

    float* out_s = (float*)d_out;
    float* out_v = out_s + (size_t)NA*FD;

    float *pX,*pH,*pGM,*pY,*pv0,*pv1,*pb1,*pt;
    unsigned short *pBh,*pBl;
    cudaGetSymbolAddress((void**)&pX,  g_X);
    cudaGetSymbolAddress((void**)&pH,  g_H);
    cudaGetSymbolAddress((void**)&pGM, g_GM);
    cudaGetSymbolAddress((void**)&pY,  g_Y);
    cudaGetSymbolAddress((void**)&pv0, g_v0);
    cudaGetSymbolAddress((void**)&pv1, g_v1);
    cudaGetSymbolAddress((void**)&pb1, g_b1c);
    cudaGetSymbolAddress((void**)&pt,  g_tbuf);
    cudaGetSymbolAddress((void**)&pBh, g_Bh);
    cudaGetSymbolAddress((void**)&pBl, g_Bl);

    cudaMemcpyAsync(out_s, features, (size_t)NA*FD*sizeof(float), cudaMemcpyDeviceToDevice, 0);
    cudaMemsetAsync(pv0, 0, (size_t)NA*96*sizeof(float), 0);
    prep_u_k<<<(PE*3+255)/256, 256>>>(vectors, distances);

    const int MT = (NA+127)/128;   // node-row tiles

    for(int b=0;b<2;b++){
        const float* eqW1 = b ? eq1_W1 : eq0_W1;
        const float* eqb1 = b ? eq1_b1 : eq0_b1;
        const float* eqW2 = b ? eq1_W2 : eq0_W2;
        float* v_in  = b ? pv1  : pv0;
        float* v_out = b ? out_v: pv1;
        const int KW = b ? KW1 : 64;

        // Y = s @ [W1i_eff | W1j_eff]   (NA,128)@(128,512)
        prep_wy_k<<<(YW*FD+255)/256, 256>>>(b, Wrbf, eqW1, inv_W1);
        { dim3 g(4, MT);
          gemm_k<<<g,256>>>(out_s, FD, FD, nullptr, 0, pBh, pBl, nullptr,
                            nullptr, nullptr, nullptr, pY, YW, NA, YW, FD, NOACT, 0); }

        prep_w1split_k<<<(KW*DH+255)/256, 256>>>(b, KW, Wrbf, eqW1, eqb1, inv_W1, inv_b1);
        if(b) edge_x_k<<<PE/8, dim3(32,8)>>>(v_in, idx_i, idx_j);

        // H = silu(rbf@W1r [+ a@W1a] + Y_i + Y_j + b1)
        { dim3 g(2, PE/128);
          gemm_k<<<g,256>>>(rbfs, RD, 64, pX, KA, pBh, pBl, pb1,
                            pY, idx_i, idx_j, pH, DH, PE, DH, KW, 0, 0); }

        // G = H_eq @ eqW2   (P,128)@(128,64), raw
        prep_w2g_k<<<(64*FD+255)/256, 256>>>(eqW2);
        { dim3 g(1, PE/128);
          gemm_k<<<g,256>>>(pH, DH, FD, nullptr, 0, pBh, pBl, nullptr,
                            nullptr, nullptr, nullptr, pGM, DG, PE, 64, FD, NOACT, 0); }
        // Mi = silu(H_inv @ invW2 + invb2)  (P,128)@(128,128)
        prep_w2m_k<<<(FD*FD+255)/256, 256>>>(b, inv_W2);
        { dim3 g(1, PE/128);
          gemm_k<<<g,256>>>(pH+FD, DH, FD, nullptr, 0, pBh, pBl, inv_b2 + b*FD,
                            nullptr, nullptr, nullptr, pGM+64, DG, PE, FD, FD, 0, 0); }

        // v_out = v_in + segment_sum(dv)
        cudaMemcpyAsync(v_out, v_in, (size_t)NA*96*sizeof(float), cudaMemcpyDeviceToDevice, 0);
        dv_scatter_k<<<PE/128, 96>>>(v_in, v_out, idx_i, idx_j, cutoffs);
        // s += segment_sum(m)
        m_scatter_k<<<PE/128, 128>>>(out_s, idx_i, cutoffs);

        // node update (Wemb folded into U1)
        prep_u1split_k<<<(FD*FD+255)/256, 256>>>(upd_W1 + (size_t)b*2*FD*FD, Wemb);
        { dim3 g(1, MT);
          gemm_k<<<g,256>>>(out_s, FD, FD, nullptr, 0, pBh, pBl, upd_b1 + b*FD,
                            nullptr, nullptr, nullptr, pt, FD, NA, FD, FD, 0, 0); }
        prep_u2split_k<<<(FD*FD+255)/256, 256>>>(upd_W2 + (size_t)b*FD*FD);
        { dim3 g(1, MT);
          gemm_k<<<g,256>>>(pt, FD, FD, nullptr, 0, pBh, pBl, upd_b2 + b*FD,
                            nullptr, nullptr, nullptr, out_s, FD, NA, FD, FD, 0, 1); }
    }
    (void)in_sizes; (void)n_in; (void)out_size;
}